// round 14
// baseline (speedup 1.0000x reference)
#include <cuda_runtime.h>
#include <cstddef>
#include <cstdint>

// ---------------------------------------------------------------------------
// HMP hierarchical message passing — R14: bf16-split mma, 2 tiles/warp,
// vectorized fragment loads.
//  * 128-thr blocks, 4 warps x 2 m16-tiles (32 rows/warp), 128-row block tile
//  * x staged as interleaved (hi,lo) bf16x2 pairs; A frags via LDS.64
//  * weights nt-interleaved, pair stride 40: one LDS.128 = b0 for 4 nt
//  * hl+lh share one accumulator (reassociation only) -> ~145 regs, 3 blk/SM
// ---------------------------------------------------------------------------

typedef unsigned int uint32;

#define N1MAX 250000
#define N2MAX 500000
#define N3MAX 1000000

__device__ float g_h2   [(size_t)N2MAX * 32];
__device__ float g_h3   [(size_t)N3MAX * 32];
__device__ float g_acc3 [(size_t)N3MAX * 32];
__device__ float g_acc2 [(size_t)N2MAX * 32];
__device__ float g_acc1 [(size_t)N1MAX * 32];
__device__ float g_accr [(size_t)N1MAX * 32];
__device__ float g_h1mid[(size_t)N1MAX * 32];

// ---------------------------------------------------------------------------
__device__ __forceinline__ float tanh_fast(float x)
{
    float cx = fminf(fmaxf(x, -15.f), 15.f);
    float e  = __expf(2.f * cx);
    return __fdividef(e - 1.f, e + 1.f);
}

// split (v0,v1) into packed bf16 hi pair (truncated) + bf16 lo pair (residual)
__device__ __forceinline__ void split2_bf16(float v0, float v1,
                                            uint32& hi, uint32& lo)
{
    uint32 u0 = __float_as_uint(v0), u1 = __float_as_uint(v1);
    hi = (u1 & 0xFFFF0000u) | (u0 >> 16);
    float l0 = v0 - __uint_as_float(u0 & 0xFFFF0000u);
    float l1 = v1 - __uint_as_float(u1 & 0xFFFF0000u);
    asm("cvt.rn.bf16x2.f32 %0, %1, %2;" : "=r"(lo) : "f"(l1), "f"(l0));
}

__device__ __forceinline__ void mma16(float c[4], const uint32 a[4],
                                      uint32 b0, uint32 b1)
{
    asm volatile(
        "mma.sync.aligned.m16n8k16.row.col.f32.bf16.bf16.f32 "
        "{%0,%1,%2,%3},{%4,%5,%6,%7},{%8,%9},{%0,%1,%2,%3};"
        : "+f"(c[0]), "+f"(c[1]), "+f"(c[2]), "+f"(c[3])
        : "r"(a[0]), "r"(a[1]), "r"(a[2]), "r"(a[3]), "r"(b0), "r"(b1));
}

// ---------------------------------------------------------------------------
__global__ void __launch_bounds__(256) zero_multi_kernel(
    float4* __restrict__ p0, int n0, float4* __restrict__ p1, int n1,
    float4* __restrict__ p2, int n2, float4* __restrict__ p3, int n3,
    float4* __restrict__ p4, int n4)
{
    const float4 z = make_float4(0.f, 0.f, 0.f, 0.f);
    int total = n0 + n1 + n2 + n3 + n4;
    for (int i = blockIdx.x * 256 + threadIdx.x; i < total; i += gridDim.x * 256) {
        int j = i;
        if (j < n0) { p0[j] = z; continue; } j -= n0;
        if (j < n1) { p1[j] = z; continue; } j -= n1;
        if (j < n2) { p2[j] = z; continue; } j -= n2;
        if (j < n3) { p3[j] = z; continue; } j -= n3;
        p4[j] = z;
    }
}

// ---------------------------------------------------------------------------
// bf16-split tensor-core MLP. 128-row tile, 4 warps, 2 m16-tiles per warp.
// x = [ self[r] | blocks from 'other' ], P blocks of 32 (P=2 or 3).
// out[r] = tanh(x@W1+b1)@W2+b2
// Weight layout: w[p * 40 + (n&7)*4 + (n>>3)]  (pair p along k, col n)
// x layout:      xs[row * XS + 2*p + {0:hi, 1:lo}],  XS = 2*KP + 8
template<int P, bool GATHER>
__global__ void __launch_bounds__(128, 3) mlp_bf2_kernel(
    const float* __restrict__ self, const float* __restrict__ other,
    const int* __restrict__ gi0, const int* __restrict__ gi1,
    const float* __restrict__ W1, const float* __restrict__ b1,
    const float* __restrict__ W2, const float* __restrict__ b2,
    float* __restrict__ out, int n)
{
    extern __shared__ uint32 smu[];
    const int KP = P * 16;          // k-pairs, layer 1
    const int XS = 2 * KP + 8;      // xs row stride (u32)
    uint32* xs  = smu;                         // [128][XS] interleaved hi/lo
    uint32* w1h = xs + 128 * XS;               // [KP][40]
    uint32* w1l = w1h + KP * 40;
    uint32* w2h = w1l + KP * 40;               // [16][40]
    uint32* w2l = w2h + 16 * 40;
    float*  b1s = (float*)(w2l + 16 * 40);     // [32]
    float*  b2s = b1s + 32;                    // [32]

    int tid  = threadIdx.x;
    int tile = blockIdx.x * 128;

    // ---- weights: load + bf16 split, nt-interleaved layout ----
    for (int idx = tid; idx < KP * 32; idx += 128) {
        int p = idx >> 5, nn = idx & 31;
        float v0 = W1[(2 * p) * 32 + nn];
        float v1 = W1[(2 * p + 1) * 32 + nn];
        uint32 hi, lo; split2_bf16(v0, v1, hi, lo);
        int o = p * 40 + (nn & 7) * 4 + (nn >> 3);
        w1h[o] = hi; w1l[o] = lo;
    }
    for (int idx = tid; idx < 16 * 32; idx += 128) {
        int p = idx >> 5, nn = idx & 31;
        float v0 = W2[(2 * p) * 32 + nn];
        float v1 = W2[(2 * p + 1) * 32 + nn];
        uint32 hi, lo; split2_bf16(v0, v1, hi, lo);
        int o = p * 40 + (nn & 7) * 4 + (nn >> 3);
        w2h[o] = hi; w2l[o] = lo;
    }
    if (tid < 32) { b1s[tid] = b1[tid]; b2s[tid] = b2[tid]; }

    // ---- stage x tile: coalesced gather + split, STS.128 per float4 ----
    {
        int rl = tid >> 3;       // 0..15
        int c  = tid & 7;        // float4 index in 32-float block
        for (int pass = 0; pass < 8; pass++) {
            int row = rl + pass * 16;
            int r = min(tile + row, n - 1);
#pragma unroll
            for (int p = 0; p < P; p++) {
                const float* src;
                if (p == 0)      src = self + (size_t)r * 32;
                else if (GATHER) src = other + (size_t)((p == 1) ? gi0[r] : gi1[r]) * 32;
                else             src = other + (size_t)r * 32;
                float4 v = ((const float4*)src)[c];
                uint32 h0, l0, h1, l1;
                split2_bf16(v.x, v.y, h0, l0);
                split2_bf16(v.z, v.w, h1, l1);
                // pairs 2c, 2c+1 of block p -> xs[..][2*(p*16+2c) + 0..3]
                uint4 w4; w4.x = h0; w4.y = l0; w4.z = h1; w4.w = l1;
                *(uint4*)(xs + row * XS + (p * 16 + 2 * c) * 2) = w4;
            }
        }
    }
    __syncthreads();

    int lane = tid & 31;
    int warp = tid >> 5;       // 0..3
    int g    = lane >> 2;
    int t4   = lane & 3;
    int rowb = warp * 32;      // 32 rows per warp, 2 tiles of 16

    // ---------------- layer 1: 2 tiles x (chh, clo) ----------------
    float chh[2][4][4], clo[2][4][4];
#pragma unroll
    for (int mt = 0; mt < 2; mt++)
#pragma unroll
        for (int nt = 0; nt < 4; nt++) {
            int col0 = nt * 8 + 2 * t4;
            chh[mt][nt][0] = b1s[col0];      chh[mt][nt][1] = b1s[col0 + 1];
            chh[mt][nt][2] = chh[mt][nt][0]; chh[mt][nt][3] = chh[mt][nt][1];
#pragma unroll
            for (int q = 0; q < 4; q++) clo[mt][nt][q] = 0.f;
        }
    {
#pragma unroll
        for (int ks = 0; ks < 2 * P; ks++) {
            int pb = ks * 8;
            uint32 ah[2][4], al[2][4];
#pragma unroll
            for (int mt = 0; mt < 2; mt++) {
                int rbase = rowb + mt * 16;
                uint2 u;
                u = *(uint2*)(xs + (rbase + g)     * XS + 2 * (pb + t4));
                ah[mt][0] = u.x; al[mt][0] = u.y;
                u = *(uint2*)(xs + (rbase + 8 + g) * XS + 2 * (pb + t4));
                ah[mt][1] = u.x; al[mt][1] = u.y;
                u = *(uint2*)(xs + (rbase + g)     * XS + 2 * (pb + t4 + 4));
                ah[mt][2] = u.x; al[mt][2] = u.y;
                u = *(uint2*)(xs + (rbase + 8 + g) * XS + 2 * (pb + t4 + 4));
                ah[mt][3] = u.x; al[mt][3] = u.y;
            }
            uint4 bh0 = *(uint4*)(w1h + (pb + t4) * 40 + g * 4);
            uint4 bh1 = *(uint4*)(w1h + (pb + t4 + 4) * 40 + g * 4);
            uint4 bl0 = *(uint4*)(w1l + (pb + t4) * 40 + g * 4);
            uint4 bl1 = *(uint4*)(w1l + (pb + t4 + 4) * 40 + g * 4);
            const uint32* bh0a = (const uint32*)&bh0;
            const uint32* bh1a = (const uint32*)&bh1;
            const uint32* bl0a = (const uint32*)&bl0;
            const uint32* bl1a = (const uint32*)&bl1;
#pragma unroll
            for (int mt = 0; mt < 2; mt++)
#pragma unroll
                for (int nt = 0; nt < 4; nt++) {
                    mma16(chh[mt][nt], ah[mt], bh0a[nt], bh1a[nt]);
                    mma16(clo[mt][nt], ah[mt], bl0a[nt], bl1a[nt]);
                    mma16(clo[mt][nt], al[mt], bh0a[nt], bh1a[nt]);
                }
        }
    }

    // ---- combine + tanh + build layer-2 A fragments in registers ----
    uint32 Ah[2][2][4], Al[2][2][4];   // [tile][ks2][a-regs]
#pragma unroll
    for (int mt = 0; mt < 2; mt++)
#pragma unroll
        for (int nt = 0; nt < 4; nt++) {
            float v0 = tanh_fast(chh[mt][nt][0] + clo[mt][nt][0]);
            float v1 = tanh_fast(chh[mt][nt][1] + clo[mt][nt][1]);
            float v2 = tanh_fast(chh[mt][nt][2] + clo[mt][nt][2]);
            float v3 = tanh_fast(chh[mt][nt][3] + clo[mt][nt][3]);
            int ks = nt >> 1, sl = (nt & 1) * 2;
            split2_bf16(v0, v1, Ah[mt][ks][sl + 0], Al[mt][ks][sl + 0]); // row g
            split2_bf16(v2, v3, Ah[mt][ks][sl + 1], Al[mt][ks][sl + 1]); // row g+8
        }

    // ---------------- layer 2: 2 tiles x (dhh, dlo) ----------------
    float dhh[2][4][4], dlo[2][4][4];
#pragma unroll
    for (int mt = 0; mt < 2; mt++)
#pragma unroll
        for (int nt = 0; nt < 4; nt++) {
            int col0 = nt * 8 + 2 * t4;
            dhh[mt][nt][0] = b2s[col0];      dhh[mt][nt][1] = b2s[col0 + 1];
            dhh[mt][nt][2] = dhh[mt][nt][0]; dhh[mt][nt][3] = dhh[mt][nt][1];
#pragma unroll
            for (int q = 0; q < 4; q++) dlo[mt][nt][q] = 0.f;
        }
#pragma unroll
    for (int ks = 0; ks < 2; ks++) {
        int pb = ks * 8;
        uint4 bh0 = *(uint4*)(w2h + (pb + t4) * 40 + g * 4);
        uint4 bh1 = *(uint4*)(w2h + (pb + t4 + 4) * 40 + g * 4);
        uint4 bl0 = *(uint4*)(w2l + (pb + t4) * 40 + g * 4);
        uint4 bl1 = *(uint4*)(w2l + (pb + t4 + 4) * 40 + g * 4);
        const uint32* bh0a = (const uint32*)&bh0;
        const uint32* bh1a = (const uint32*)&bh1;
        const uint32* bl0a = (const uint32*)&bl0;
        const uint32* bl1a = (const uint32*)&bl1;
#pragma unroll
        for (int mt = 0; mt < 2; mt++)
#pragma unroll
            for (int nt = 0; nt < 4; nt++) {
                mma16(dhh[mt][nt], Ah[mt][ks], bh0a[nt], bh1a[nt]);
                mma16(dlo[mt][nt], Ah[mt][ks], bl0a[nt], bl1a[nt]);
                mma16(dlo[mt][nt], Al[mt][ks], bh0a[nt], bh1a[nt]);
            }
    }

    // ---- combine + store ----
#pragma unroll
    for (int mt = 0; mt < 2; mt++) {
        int r0g = tile + rowb + mt * 16 + g;
        int r1g = r0g + 8;
#pragma unroll
        for (int nt = 0; nt < 4; nt++) {
            int col0 = nt * 8 + 2 * t4;
            float v0 = dhh[mt][nt][0] + dlo[mt][nt][0];
            float v1 = dhh[mt][nt][1] + dlo[mt][nt][1];
            float v2 = dhh[mt][nt][2] + dlo[mt][nt][2];
            float v3 = dhh[mt][nt][3] + dlo[mt][nt][3];
            if (r0g < n)
                *(float2*)(out + (size_t)r0g * 32 + col0) = make_float2(v0, v1);
            if (r1g < n)
                *(float2*)(out + (size_t)r1g * 32 + col0) = make_float2(v2, v3);
        }
    }
}

// ---------------------------------------------------------------------------
// acc[i0[r]] += src[r]; acc[i1[r]] += src[r]   (row-wise float4 atomics)
__global__ void __launch_bounds__(256) scatter2_kernel(
    const float* __restrict__ src,
    const int* __restrict__ i0, const int* __restrict__ i1,
    float* __restrict__ acc, int n)
{
    int r = blockIdx.x * 256 + threadIdx.x;
    if (r >= n) return;
    const float4* s = (const float4*)(src + (size_t)r * 32);
    float4* d0 = (float4*)(acc + (size_t)i0[r] * 32);
    float4* d1 = (float4*)(acc + (size_t)i1[r] * 32);
#pragma unroll
    for (int q = 0; q < 8; q++) {
        float4 v = s[q];
        atomicAdd(d0 + q, v);
        atomicAdd(d1 + q, v);
    }
}

// acc[dstidx[r]] += src[srcidx[r]]
__global__ void __launch_bounds__(256) scatter1_kernel(
    const float* __restrict__ src,
    const int* __restrict__ srcidx, const int* __restrict__ dstidx,
    float* __restrict__ acc, int n)
{
    int r = blockIdx.x * 256 + threadIdx.x;
    if (r >= n) return;
    const float4* s = (const float4*)(src + (size_t)srcidx[r] * 32);
    float4* d = (float4*)(acc + (size_t)dstidx[r] * 32);
#pragma unroll
    for (int q = 0; q < 8; q++) atomicAdd(d + q, s[q]);
}

// ---------------------------------------------------------------------------
static inline int nblk256(int n)  { return (n + 255) / 256; }
static inline int nblk128t(int n) { return (n + 127) / 128; }

static inline int smem_bytes(int P)
{
    int KP = P * 16, XS = 2 * KP + 8;
    int u32s = 128 * XS + 2 * KP * 40 + 2 * 16 * 40 + 64;
    return u32s * 4;
}

extern "C" void kernel_launch(void* const* d_in, const int* in_sizes, int n_in,
                              void* d_out, int out_size)
{
    const float* h1     = (const float*)d_in[0];
    const float* h2     = (const float*)d_in[1];
    const float* h3     = (const float*)d_in[2];
    const float* h4     = (const float*)d_in[3];
    const float* upW1   = (const float*)d_in[4];
    const float* upb1   = (const float*)d_in[5];
    const float* upW2   = (const float*)d_in[6];
    const float* upb2   = (const float*)d_in[7];
    const float* dnW1   = (const float*)d_in[8];
    const float* dnb1   = (const float*)d_in[9];
    const float* dnW2   = (const float*)d_in[10];
    const float* dnb2   = (const float*)d_in[11];
    const float* rW1    = (const float*)d_in[12];
    const float* rb1    = (const float*)d_in[13];
    const float* rW2    = (const float*)d_in[14];
    const float* rb2    = (const float*)d_in[15];
    const int* idx2_0   = (const int*)d_in[16];
    const int* idx2_1   = (const int*)d_in[17];
    const int* idx3_0   = (const int*)d_in[18];
    const int* idx3_1   = (const int*)d_in[19];
    const int* idx4_0   = (const int*)d_in[20];
    const int* idx4_1   = (const int*)d_in[21];
    const int* ring_src = (const int*)d_in[22];
    const int* ring_dst = (const int*)d_in[23];

    const int N1 = in_sizes[0] / 32;
    const int N2 = in_sizes[1] / 32;
    const int N3 = in_sizes[2] / 32;
    const int N4 = in_sizes[3] / 32;
    const int ER = in_sizes[22];
    const int NR = out_size / 32 - (N1 + N2 + N3 + N4);

    float* out  = (float*)d_out;
    float* out1 = out;
    float* out2 = out1 + (size_t)N1 * 32;
    float* out3 = out2 + (size_t)N2 * 32;
    float* out4 = out3 + (size_t)N3 * 32;
    float* outR = out4 + (size_t)N4 * 32;

    float *h2buf, *h3buf, *acc3, *acc2, *acc1, *accr, *h1mid;
    cudaGetSymbolAddress((void**)&h2buf, g_h2);
    cudaGetSymbolAddress((void**)&h3buf, g_h3);
    cudaGetSymbolAddress((void**)&acc3,  g_acc3);
    cudaGetSymbolAddress((void**)&acc2,  g_acc2);
    cudaGetSymbolAddress((void**)&acc1,  g_acc1);
    cudaGetSymbolAddress((void**)&accr,  g_accr);
    cudaGetSymbolAddress((void**)&h1mid, g_h1mid);

    const int SM3 = smem_bytes(3);
    const int SM2 = smem_bytes(2);
    cudaFuncSetAttribute(mlp_bf2_kernel<3, true>,
        cudaFuncAttributeMaxDynamicSharedMemorySize, SM3);
    cudaFuncSetAttribute(mlp_bf2_kernel<2, false>,
        cudaFuncAttributeMaxDynamicSharedMemorySize, SM2);

    // ---- zero all accumulators once ----
    zero_multi_kernel<<<2048, 256>>>(
        (float4*)acc3, N3 * 8, (float4*)acc2, N2 * 8,
        (float4*)acc1, N1 * 8, (float4*)accr, N1 * 8,
        (float4*)outR, NR * 8);

    // ---- up pass ----
    mlp_bf2_kernel<3, true><<<nblk128t(N2), 128, SM3>>>(h2, h1, idx2_0, idx2_1,
        upW1 + 0 * 96 * 32, upb1 + 0 * 32, upW2 + 0 * 1024, upb2 + 0 * 32,
        h2buf, N2);
    mlp_bf2_kernel<3, true><<<nblk128t(N3), 128, SM3>>>(h3, h2buf, idx3_0, idx3_1,
        upW1 + 1 * 96 * 32, upb1 + 1 * 32, upW2 + 1 * 1024, upb2 + 1 * 32,
        h3buf, N3);
    mlp_bf2_kernel<3, true><<<nblk128t(N4), 128, SM3>>>(h4, h3buf, idx4_0, idx4_1,
        upW1 + 2 * 96 * 32, upb1 + 2 * 32, upW2 + 2 * 1024, upb2 + 2 * 32,
        out4, N4);

    // ---- down pass ----
    scatter2_kernel<<<nblk256(N4), 256>>>(out4, idx4_0, idx4_1, acc3, N4);
    mlp_bf2_kernel<2, false><<<nblk128t(N3), 128, SM2>>>(h3buf, acc3, 0, 0,
        dnW1 + 2 * 64 * 32, dnb1 + 2 * 32, dnW2 + 2 * 1024, dnb2 + 2 * 32,
        out3, N3);

    scatter2_kernel<<<nblk256(N3), 256>>>(out3, idx3_0, idx3_1, acc2, N3);
    mlp_bf2_kernel<2, false><<<nblk128t(N2), 128, SM2>>>(h2buf, acc2, 0, 0,
        dnW1 + 1 * 64 * 32, dnb1 + 1 * 32, dnW2 + 1 * 1024, dnb2 + 1 * 32,
        out2, N2);

    scatter2_kernel<<<nblk256(N2), 256>>>(out2, idx2_0, idx2_1, acc1, N2);
    mlp_bf2_kernel<2, false><<<nblk128t(N1), 128, SM2>>>(h1, acc1, 0, 0,
        dnW1 + 0 * 64 * 32, dnb1 + 0 * 32, dnW2 + 0 * 1024, dnb2 + 0 * 32,
        h1mid, N1);

    // ---- ring ----
    scatter1_kernel<<<nblk256(ER), 256>>>(h1mid, ring_src, ring_dst, outR, ER);
    scatter1_kernel<<<nblk256(ER), 256>>>(outR, ring_dst, ring_src, accr, ER);
    mlp_bf2_kernel<2, false><<<nblk128t(N1), 128, SM2>>>(h1mid, accr, 0, 0,
        rW1, rb1, rW2, rb2, out1, N1);
}

// round 15
// speedup vs baseline: 1.1610x; 1.1610x over previous
#include <cuda_runtime.h>
#include <cstddef>
#include <cstdint>

// ---------------------------------------------------------------------------
// HMP hierarchical message passing — R15: R13 tiling + R14 vector layouts.
//  * 256-thr blocks, 8 warps x 16 rows (R13 tiling, 16 warps/SM)
//  * weights nt-interleaved stride-40: B frag = 4 LDS.128 / ks (R14 layout)
//  * x staged as interleaved (hi,lo) bf16x2 pairs: A frag = 4 LDS.64 / ks
//  * hl+lh share one accumulator; layer-2 A frags in registers
// ---------------------------------------------------------------------------

typedef unsigned int uint32;

#define N1MAX 250000
#define N2MAX 500000
#define N3MAX 1000000

__device__ float g_h2   [(size_t)N2MAX * 32];
__device__ float g_h3   [(size_t)N3MAX * 32];
__device__ float g_acc3 [(size_t)N3MAX * 32];
__device__ float g_acc2 [(size_t)N2MAX * 32];
__device__ float g_acc1 [(size_t)N1MAX * 32];
__device__ float g_accr [(size_t)N1MAX * 32];
__device__ float g_h1mid[(size_t)N1MAX * 32];

// ---------------------------------------------------------------------------
__device__ __forceinline__ float tanh_fast(float x)
{
    float cx = fminf(fmaxf(x, -15.f), 15.f);
    float e  = __expf(2.f * cx);
    return __fdividef(e - 1.f, e + 1.f);
}

// split (v0,v1) into packed bf16 hi pair (truncated) + bf16 lo pair (residual)
__device__ __forceinline__ void split2_bf16(float v0, float v1,
                                            uint32& hi, uint32& lo)
{
    uint32 u0 = __float_as_uint(v0), u1 = __float_as_uint(v1);
    hi = (u1 & 0xFFFF0000u) | (u0 >> 16);
    float l0 = v0 - __uint_as_float(u0 & 0xFFFF0000u);
    float l1 = v1 - __uint_as_float(u1 & 0xFFFF0000u);
    asm("cvt.rn.bf16x2.f32 %0, %1, %2;" : "=r"(lo) : "f"(l1), "f"(l0));
}

__device__ __forceinline__ void mma16(float c[4], const uint32 a[4],
                                      uint32 b0, uint32 b1)
{
    asm volatile(
        "mma.sync.aligned.m16n8k16.row.col.f32.bf16.bf16.f32 "
        "{%0,%1,%2,%3},{%4,%5,%6,%7},{%8,%9},{%0,%1,%2,%3};"
        : "+f"(c[0]), "+f"(c[1]), "+f"(c[2]), "+f"(c[3])
        : "r"(a[0]), "r"(a[1]), "r"(a[2]), "r"(a[3]), "r"(b0), "r"(b1));
}

// ---------------------------------------------------------------------------
__global__ void __launch_bounds__(256) zero_multi_kernel(
    float4* __restrict__ p0, int n0, float4* __restrict__ p1, int n1,
    float4* __restrict__ p2, int n2, float4* __restrict__ p3, int n3,
    float4* __restrict__ p4, int n4)
{
    const float4 z = make_float4(0.f, 0.f, 0.f, 0.f);
    int total = n0 + n1 + n2 + n3 + n4;
    for (int i = blockIdx.x * 256 + threadIdx.x; i < total; i += gridDim.x * 256) {
        int j = i;
        if (j < n0) { p0[j] = z; continue; } j -= n0;
        if (j < n1) { p1[j] = z; continue; } j -= n1;
        if (j < n2) { p2[j] = z; continue; } j -= n2;
        if (j < n3) { p3[j] = z; continue; } j -= n3;
        p4[j] = z;
    }
}

// ---------------------------------------------------------------------------
// bf16-split tensor-core MLP. 128-row tile, 8 warps, 16 rows/warp.
// x = [ self[r] | blocks from 'other' ], P blocks of 32 (P=2 or 3).
// out[r] = tanh(x@W1+b1)@W2+b2
// Weight layout: w[p * 40 + (n&7)*4 + (n>>3)]  (pair p along k, col n)
// x layout:      xs[row * XS + 2*(pairIndex) + {0:hi, 1:lo}], XS = 2*KP + 8
template<int P, bool GATHER>
__global__ void __launch_bounds__(256) mlp_bf3_kernel(
    const float* __restrict__ self, const float* __restrict__ other,
    const int* __restrict__ gi0, const int* __restrict__ gi1,
    const float* __restrict__ W1, const float* __restrict__ b1,
    const float* __restrict__ W2, const float* __restrict__ b2,
    float* __restrict__ out, int n)
{
    extern __shared__ uint32 smu[];
    const int KP = P * 16;          // k-pairs, layer 1
    const int XS = 2 * KP + 8;      // xs row stride (u32)
    uint32* xs  = smu;                         // [128][XS] interleaved hi/lo
    uint32* w1h = xs + 128 * XS;               // [KP][40]
    uint32* w1l = w1h + KP * 40;
    uint32* w2h = w1l + KP * 40;               // [16][40]
    uint32* w2l = w2h + 16 * 40;
    float*  b1s = (float*)(w2l + 16 * 40);     // [32]
    float*  b2s = b1s + 32;                    // [32]

    int tid  = threadIdx.x;
    int tile = blockIdx.x * 128;

    // ---- weights: load + bf16 split, nt-interleaved layout ----
    for (int idx = tid; idx < KP * 32; idx += 256) {
        int p = idx >> 5, nn = idx & 31;
        float v0 = W1[(2 * p) * 32 + nn];
        float v1 = W1[(2 * p + 1) * 32 + nn];
        uint32 hi, lo; split2_bf16(v0, v1, hi, lo);
        int o = p * 40 + (nn & 7) * 4 + (nn >> 3);
        w1h[o] = hi; w1l[o] = lo;
    }
    for (int idx = tid; idx < 16 * 32; idx += 256) {
        int p = idx >> 5, nn = idx & 31;
        float v0 = W2[(2 * p) * 32 + nn];
        float v1 = W2[(2 * p + 1) * 32 + nn];
        uint32 hi, lo; split2_bf16(v0, v1, hi, lo);
        int o = p * 40 + (nn & 7) * 4 + (nn >> 3);
        w2h[o] = hi; w2l[o] = lo;
    }
    if (tid < 32) { b1s[tid] = b1[tid]; b2s[tid] = b2[tid]; }

    // ---- stage x tile: coalesced gather + split, STS.128 per float4 ----
    {
        int rl = tid >> 3;       // 0..31
        int c  = tid & 7;        // float4 index in 32-float block
        for (int pass = 0; pass < 4; pass++) {
            int row = rl + pass * 32;
            int r = min(tile + row, n - 1);
#pragma unroll
            for (int p = 0; p < P; p++) {
                const float* src;
                if (p == 0)      src = self + (size_t)r * 32;
                else if (GATHER) src = other + (size_t)((p == 1) ? gi0[r] : gi1[r]) * 32;
                else             src = other + (size_t)r * 32;
                float4 v = ((const float4*)src)[c];
                uint32 h0, l0, h1, l1;
                split2_bf16(v.x, v.y, h0, l0);
                split2_bf16(v.z, v.w, h1, l1);
                uint4 w4; w4.x = h0; w4.y = l0; w4.z = h1; w4.w = l1;
                *(uint4*)(xs + row * XS + (p * 16 + 2 * c) * 2) = w4;
            }
        }
    }
    __syncthreads();

    int lane = tid & 31;
    int warp = tid >> 5;       // 0..7
    int g    = lane >> 2;
    int t4   = lane & 3;
    int rowb = warp * 16;

    // ---------------- layer 1: (chh, clo) ----------------
    float chh[4][4], clo[4][4];
#pragma unroll
    for (int nt = 0; nt < 4; nt++) {
        int col0 = nt * 8 + 2 * t4;
        chh[nt][0] = b1s[col0];  chh[nt][1] = b1s[col0 + 1];
        chh[nt][2] = chh[nt][0]; chh[nt][3] = chh[nt][1];
#pragma unroll
        for (int q = 0; q < 4; q++) clo[nt][q] = 0.f;
    }
    {
        const uint32* x0 = xs + (rowb + g) * XS;
        const uint32* x1 = xs + (rowb + 8 + g) * XS;
#pragma unroll
        for (int ks = 0; ks < 2 * P; ks++) {
            int pb = ks * 8;
            uint32 ah[4], al[4];
            uint2 u;
            u = *(uint2*)(x0 + 2 * (pb + t4));     ah[0] = u.x; al[0] = u.y;
            u = *(uint2*)(x1 + 2 * (pb + t4));     ah[1] = u.x; al[1] = u.y;
            u = *(uint2*)(x0 + 2 * (pb + t4 + 4)); ah[2] = u.x; al[2] = u.y;
            u = *(uint2*)(x1 + 2 * (pb + t4 + 4)); ah[3] = u.x; al[3] = u.y;
            uint4 bh0 = *(uint4*)(w1h + (pb + t4) * 40 + g * 4);
            uint4 bh1 = *(uint4*)(w1h + (pb + t4 + 4) * 40 + g * 4);
            uint4 bl0 = *(uint4*)(w1l + (pb + t4) * 40 + g * 4);
            uint4 bl1 = *(uint4*)(w1l + (pb + t4 + 4) * 40 + g * 4);
            const uint32* bh0a = (const uint32*)&bh0;
            const uint32* bh1a = (const uint32*)&bh1;
            const uint32* bl0a = (const uint32*)&bl0;
            const uint32* bl1a = (const uint32*)&bl1;
#pragma unroll
            for (int nt = 0; nt < 4; nt++) {
                mma16(chh[nt], ah, bh0a[nt], bh1a[nt]);
                mma16(clo[nt], ah, bl0a[nt], bl1a[nt]);
                mma16(clo[nt], al, bh0a[nt], bh1a[nt]);
            }
        }
    }

    // ---- combine + tanh + build layer-2 A fragments in registers ----
    uint32 Ah[2][4], Al[2][4];
#pragma unroll
    for (int nt = 0; nt < 4; nt++) {
        float v0 = tanh_fast(chh[nt][0] + clo[nt][0]);
        float v1 = tanh_fast(chh[nt][1] + clo[nt][1]);
        float v2 = tanh_fast(chh[nt][2] + clo[nt][2]);
        float v3 = tanh_fast(chh[nt][3] + clo[nt][3]);
        int ks = nt >> 1, sl = (nt & 1) * 2;
        split2_bf16(v0, v1, Ah[ks][sl + 0], Al[ks][sl + 0]);   // row g
        split2_bf16(v2, v3, Ah[ks][sl + 1], Al[ks][sl + 1]);   // row g+8
    }

    // ---------------- layer 2: (dhh, dlo) ----------------
    float dhh[4][4], dlo[4][4];
#pragma unroll
    for (int nt = 0; nt < 4; nt++) {
        int col0 = nt * 8 + 2 * t4;
        dhh[nt][0] = b2s[col0];  dhh[nt][1] = b2s[col0 + 1];
        dhh[nt][2] = dhh[nt][0]; dhh[nt][3] = dhh[nt][1];
#pragma unroll
        for (int q = 0; q < 4; q++) dlo[nt][q] = 0.f;
    }
#pragma unroll
    for (int ks = 0; ks < 2; ks++) {
        int pb = ks * 8;
        uint4 bh0 = *(uint4*)(w2h + (pb + t4) * 40 + g * 4);
        uint4 bh1 = *(uint4*)(w2h + (pb + t4 + 4) * 40 + g * 4);
        uint4 bl0 = *(uint4*)(w2l + (pb + t4) * 40 + g * 4);
        uint4 bl1 = *(uint4*)(w2l + (pb + t4 + 4) * 40 + g * 4);
        const uint32* bh0a = (const uint32*)&bh0;
        const uint32* bh1a = (const uint32*)&bh1;
        const uint32* bl0a = (const uint32*)&bl0;
        const uint32* bl1a = (const uint32*)&bl1;
#pragma unroll
        for (int nt = 0; nt < 4; nt++) {
            mma16(dhh[nt], Ah[ks], bh0a[nt], bh1a[nt]);
            mma16(dlo[nt], Ah[ks], bl0a[nt], bl1a[nt]);
            mma16(dlo[nt], Al[ks], bh0a[nt], bh1a[nt]);
        }
    }

    // ---- combine + store ----
    {
        int r0g = tile + rowb + g;
        int r1g = r0g + 8;
#pragma unroll
        for (int nt = 0; nt < 4; nt++) {
            int col0 = nt * 8 + 2 * t4;
            float v0 = dhh[nt][0] + dlo[nt][0];
            float v1 = dhh[nt][1] + dlo[nt][1];
            float v2 = dhh[nt][2] + dlo[nt][2];
            float v3 = dhh[nt][3] + dlo[nt][3];
            if (r0g < n)
                *(float2*)(out + (size_t)r0g * 32 + col0) = make_float2(v0, v1);
            if (r1g < n)
                *(float2*)(out + (size_t)r1g * 32 + col0) = make_float2(v2, v3);
        }
    }
}

// ---------------------------------------------------------------------------
// acc[i0[r]] += src[r]; acc[i1[r]] += src[r]   (row-wise float4 atomics)
__global__ void __launch_bounds__(256) scatter2_kernel(
    const float* __restrict__ src,
    const int* __restrict__ i0, const int* __restrict__ i1,
    float* __restrict__ acc, int n)
{
    int r = blockIdx.x * 256 + threadIdx.x;
    if (r >= n) return;
    const float4* s = (const float4*)(src + (size_t)r * 32);
    float4* d0 = (float4*)(acc + (size_t)i0[r] * 32);
    float4* d1 = (float4*)(acc + (size_t)i1[r] * 32);
#pragma unroll
    for (int q = 0; q < 8; q++) {
        float4 v = s[q];
        atomicAdd(d0 + q, v);
        atomicAdd(d1 + q, v);
    }
}

// acc[dstidx[r]] += src[srcidx[r]]
__global__ void __launch_bounds__(256) scatter1_kernel(
    const float* __restrict__ src,
    const int* __restrict__ srcidx, const int* __restrict__ dstidx,
    float* __restrict__ acc, int n)
{
    int r = blockIdx.x * 256 + threadIdx.x;
    if (r >= n) return;
    const float4* s = (const float4*)(src + (size_t)srcidx[r] * 32);
    float4* d = (float4*)(acc + (size_t)dstidx[r] * 32);
#pragma unroll
    for (int q = 0; q < 8; q++) atomicAdd(d + q, s[q]);
}

// ---------------------------------------------------------------------------
static inline int nblk256(int n)  { return (n + 255) / 256; }
static inline int nblk128t(int n) { return (n + 127) / 128; }

static inline int smem_bytes(int P)
{
    int KP = P * 16, XS = 2 * KP + 8;
    int u32s = 128 * XS + 2 * KP * 40 + 2 * 16 * 40 + 64;
    return u32s * 4;
}

extern "C" void kernel_launch(void* const* d_in, const int* in_sizes, int n_in,
                              void* d_out, int out_size)
{
    const float* h1     = (const float*)d_in[0];
    const float* h2     = (const float*)d_in[1];
    const float* h3     = (const float*)d_in[2];
    const float* h4     = (const float*)d_in[3];
    const float* upW1   = (const float*)d_in[4];
    const float* upb1   = (const float*)d_in[5];
    const float* upW2   = (const float*)d_in[6];
    const float* upb2   = (const float*)d_in[7];
    const float* dnW1   = (const float*)d_in[8];
    const float* dnb1   = (const float*)d_in[9];
    const float* dnW2   = (const float*)d_in[10];
    const float* dnb2   = (const float*)d_in[11];
    const float* rW1    = (const float*)d_in[12];
    const float* rb1    = (const float*)d_in[13];
    const float* rW2    = (const float*)d_in[14];
    const float* rb2    = (const float*)d_in[15];
    const int* idx2_0   = (const int*)d_in[16];
    const int* idx2_1   = (const int*)d_in[17];
    const int* idx3_0   = (const int*)d_in[18];
    const int* idx3_1   = (const int*)d_in[19];
    const int* idx4_0   = (const int*)d_in[20];
    const int* idx4_1   = (const int*)d_in[21];
    const int* ring_src = (const int*)d_in[22];
    const int* ring_dst = (const int*)d_in[23];

    const int N1 = in_sizes[0] / 32;
    const int N2 = in_sizes[1] / 32;
    const int N3 = in_sizes[2] / 32;
    const int N4 = in_sizes[3] / 32;
    const int ER = in_sizes[22];
    const int NR = out_size / 32 - (N1 + N2 + N3 + N4);

    float* out  = (float*)d_out;
    float* out1 = out;
    float* out2 = out1 + (size_t)N1 * 32;
    float* out3 = out2 + (size_t)N2 * 32;
    float* out4 = out3 + (size_t)N3 * 32;
    float* outR = out4 + (size_t)N4 * 32;

    float *h2buf, *h3buf, *acc3, *acc2, *acc1, *accr, *h1mid;
    cudaGetSymbolAddress((void**)&h2buf, g_h2);
    cudaGetSymbolAddress((void**)&h3buf, g_h3);
    cudaGetSymbolAddress((void**)&acc3,  g_acc3);
    cudaGetSymbolAddress((void**)&acc2,  g_acc2);
    cudaGetSymbolAddress((void**)&acc1,  g_acc1);
    cudaGetSymbolAddress((void**)&accr,  g_accr);
    cudaGetSymbolAddress((void**)&h1mid, g_h1mid);

    const int SM3 = smem_bytes(3);
    const int SM2 = smem_bytes(2);
    cudaFuncSetAttribute(mlp_bf3_kernel<3, true>,
        cudaFuncAttributeMaxDynamicSharedMemorySize, SM3);
    cudaFuncSetAttribute(mlp_bf3_kernel<2, false>,
        cudaFuncAttributeMaxDynamicSharedMemorySize, SM2);

    // ---- zero all accumulators once ----
    zero_multi_kernel<<<2048, 256>>>(
        (float4*)acc3, N3 * 8, (float4*)acc2, N2 * 8,
        (float4*)acc1, N1 * 8, (float4*)accr, N1 * 8,
        (float4*)outR, NR * 8);

    // ---- up pass ----
    mlp_bf3_kernel<3, true><<<nblk128t(N2), 256, SM3>>>(h2, h1, idx2_0, idx2_1,
        upW1 + 0 * 96 * 32, upb1 + 0 * 32, upW2 + 0 * 1024, upb2 + 0 * 32,
        h2buf, N2);
    mlp_bf3_kernel<3, true><<<nblk128t(N3), 256, SM3>>>(h3, h2buf, idx3_0, idx3_1,
        upW1 + 1 * 96 * 32, upb1 + 1 * 32, upW2 + 1 * 1024, upb2 + 1 * 32,
        h3buf, N3);
    mlp_bf3_kernel<3, true><<<nblk128t(N4), 256, SM3>>>(h4, h3buf, idx4_0, idx4_1,
        upW1 + 2 * 96 * 32, upb1 + 2 * 32, upW2 + 2 * 1024, upb2 + 2 * 32,
        out4, N4);

    // ---- down pass ----
    scatter2_kernel<<<nblk256(N4), 256>>>(out4, idx4_0, idx4_1, acc3, N4);
    mlp_bf3_kernel<2, false><<<nblk128t(N3), 256, SM2>>>(h3buf, acc3, 0, 0,
        dnW1 + 2 * 64 * 32, dnb1 + 2 * 32, dnW2 + 2 * 1024, dnb2 + 2 * 32,
        out3, N3);

    scatter2_kernel<<<nblk256(N3), 256>>>(out3, idx3_0, idx3_1, acc2, N3);
    mlp_bf3_kernel<2, false><<<nblk128t(N2), 256, SM2>>>(h2buf, acc2, 0, 0,
        dnW1 + 1 * 64 * 32, dnb1 + 1 * 32, dnW2 + 1 * 1024, dnb2 + 1 * 32,
        out2, N2);

    scatter2_kernel<<<nblk256(N2), 256>>>(out2, idx2_0, idx2_1, acc1, N2);
    mlp_bf3_kernel<2, false><<<nblk128t(N1), 256, SM2>>>(h1, acc1, 0, 0,
        dnW1 + 0 * 64 * 32, dnb1 + 0 * 32, dnW2 + 0 * 1024, dnb2 + 0 * 32,
        h1mid, N1);

    // ---- ring ----
    scatter1_kernel<<<nblk256(ER), 256>>>(h1mid, ring_src, ring_dst, outR, ER);
    scatter1_kernel<<<nblk256(ER), 256>>>(outR, ring_dst, ring_src, accr, ER);
    mlp_bf3_kernel<2, false><<<nblk128t(N1), 256, SM2>>>(h1mid, accr, 0, 0,
        rW1, rb1, rW2, rb2, out1, N1);
}

// round 16
// speedup vs baseline: 1.4055x; 1.2106x over previous
#include <cuda_runtime.h>
#include <cstddef>
#include <cstdint>

// ---------------------------------------------------------------------------
// HMP hierarchical message passing — R16: R15 MLP + fused SMEM-staged scatter.
//  * 256-thr blocks, 8 warps x 16 rows; bf16-split mma (R15 layouts)
//  * producer MLPs scatter their output rows into acc via idx arrays:
//    fragments -> SMEM staging (reuses xs) -> cooperative float4 red ops
//  * ring scatters / zero unchanged
// ---------------------------------------------------------------------------

typedef unsigned int uint32;

#define N1MAX 250000
#define N2MAX 500000
#define N3MAX 1000000

__device__ float g_h2   [(size_t)N2MAX * 32];
__device__ float g_h3   [(size_t)N3MAX * 32];
__device__ float g_acc3 [(size_t)N3MAX * 32];
__device__ float g_acc2 [(size_t)N2MAX * 32];
__device__ float g_acc1 [(size_t)N1MAX * 32];
__device__ float g_accr [(size_t)N1MAX * 32];
__device__ float g_h1mid[(size_t)N1MAX * 32];

// ---------------------------------------------------------------------------
__device__ __forceinline__ float tanh_fast(float x)
{
    float cx = fminf(fmaxf(x, -15.f), 15.f);
    float e  = __expf(2.f * cx);
    return __fdividef(e - 1.f, e + 1.f);
}

__device__ __forceinline__ void split2_bf16(float v0, float v1,
                                            uint32& hi, uint32& lo)
{
    uint32 u0 = __float_as_uint(v0), u1 = __float_as_uint(v1);
    hi = (u1 & 0xFFFF0000u) | (u0 >> 16);
    float l0 = v0 - __uint_as_float(u0 & 0xFFFF0000u);
    float l1 = v1 - __uint_as_float(u1 & 0xFFFF0000u);
    asm("cvt.rn.bf16x2.f32 %0, %1, %2;" : "=r"(lo) : "f"(l1), "f"(l0));
}

__device__ __forceinline__ void mma16(float c[4], const uint32 a[4],
                                      uint32 b0, uint32 b1)
{
    asm volatile(
        "mma.sync.aligned.m16n8k16.row.col.f32.bf16.bf16.f32 "
        "{%0,%1,%2,%3},{%4,%5,%6,%7},{%8,%9},{%0,%1,%2,%3};"
        : "+f"(c[0]), "+f"(c[1]), "+f"(c[2]), "+f"(c[3])
        : "r"(a[0]), "r"(a[1]), "r"(a[2]), "r"(a[3]), "r"(b0), "r"(b1));
}

// ---------------------------------------------------------------------------
__global__ void __launch_bounds__(256) zero_multi_kernel(
    float4* __restrict__ p0, int n0, float4* __restrict__ p1, int n1,
    float4* __restrict__ p2, int n2, float4* __restrict__ p3, int n3,
    float4* __restrict__ p4, int n4)
{
    const float4 z = make_float4(0.f, 0.f, 0.f, 0.f);
    int total = n0 + n1 + n2 + n3 + n4;
    for (int i = blockIdx.x * 256 + threadIdx.x; i < total; i += gridDim.x * 256) {
        int j = i;
        if (j < n0) { p0[j] = z; continue; } j -= n0;
        if (j < n1) { p1[j] = z; continue; } j -= n1;
        if (j < n2) { p2[j] = z; continue; } j -= n2;
        if (j < n3) { p3[j] = z; continue; } j -= n3;
        p4[j] = z;
    }
}

// ---------------------------------------------------------------------------
// bf16-split tensor-core MLP with optional fused scatter.
// x = [ self[r] | blocks from 'other' ], P blocks of 32 (P=2 or 3).
// out[r] = tanh(x@W1+b1)@W2+b2 ; if SCATTER: acc[si0[r]] += out[r], acc[si1[r]] += out[r]
template<int P, bool GATHER, bool SCATTER>
__global__ void __launch_bounds__(256) mlp_bf3_kernel(
    const float* __restrict__ self, const float* __restrict__ other,
    const int* __restrict__ gi0, const int* __restrict__ gi1,
    const float* __restrict__ W1, const float* __restrict__ b1,
    const float* __restrict__ W2, const float* __restrict__ b2,
    float* __restrict__ out,
    float* __restrict__ acc,
    const int* __restrict__ si0, const int* __restrict__ si1,
    int n)
{
    extern __shared__ uint32 smu[];
    const int KP = P * 16;          // k-pairs, layer 1
    const int XS = 2 * KP + 8;      // xs row stride (u32)
    uint32* xs  = smu;                         // [128][XS] interleaved hi/lo
    uint32* w1h = xs + 128 * XS;               // [KP][40]
    uint32* w1l = w1h + KP * 40;
    uint32* w2h = w1l + KP * 40;               // [16][40]
    uint32* w2l = w2h + 16 * 40;
    float*  b1s = (float*)(w2l + 16 * 40);     // [32]
    float*  b2s = b1s + 32;                    // [32]
    float*  ws  = (float*)xs;                  // staging for scatter [128][36]

    int tid  = threadIdx.x;
    int tile = blockIdx.x * 128;

    // ---- weights: load + bf16 split, nt-interleaved layout ----
    for (int idx = tid; idx < KP * 32; idx += 256) {
        int p = idx >> 5, nn = idx & 31;
        float v0 = W1[(2 * p) * 32 + nn];
        float v1 = W1[(2 * p + 1) * 32 + nn];
        uint32 hi, lo; split2_bf16(v0, v1, hi, lo);
        int o = p * 40 + (nn & 7) * 4 + (nn >> 3);
        w1h[o] = hi; w1l[o] = lo;
    }
    for (int idx = tid; idx < 16 * 32; idx += 256) {
        int p = idx >> 5, nn = idx & 31;
        float v0 = W2[(2 * p) * 32 + nn];
        float v1 = W2[(2 * p + 1) * 32 + nn];
        uint32 hi, lo; split2_bf16(v0, v1, hi, lo);
        int o = p * 40 + (nn & 7) * 4 + (nn >> 3);
        w2h[o] = hi; w2l[o] = lo;
    }
    if (tid < 32) { b1s[tid] = b1[tid]; b2s[tid] = b2[tid]; }

    // ---- stage x tile ----
    {
        int rl = tid >> 3;
        int c  = tid & 7;
        for (int pass = 0; pass < 4; pass++) {
            int row = rl + pass * 32;
            int r = min(tile + row, n - 1);
#pragma unroll
            for (int p = 0; p < P; p++) {
                const float* src;
                if (p == 0)      src = self + (size_t)r * 32;
                else if (GATHER) src = other + (size_t)((p == 1) ? gi0[r] : gi1[r]) * 32;
                else             src = other + (size_t)r * 32;
                float4 v = ((const float4*)src)[c];
                uint32 h0, l0, h1, l1;
                split2_bf16(v.x, v.y, h0, l0);
                split2_bf16(v.z, v.w, h1, l1);
                uint4 w4; w4.x = h0; w4.y = l0; w4.z = h1; w4.w = l1;
                *(uint4*)(xs + row * XS + (p * 16 + 2 * c) * 2) = w4;
            }
        }
    }
    __syncthreads();

    int lane = tid & 31;
    int warp = tid >> 5;
    int g    = lane >> 2;
    int t4   = lane & 3;
    int rowb = warp * 16;

    // ---------------- layer 1: (chh, clo) ----------------
    float chh[4][4], clo[4][4];
#pragma unroll
    for (int nt = 0; nt < 4; nt++) {
        int col0 = nt * 8 + 2 * t4;
        chh[nt][0] = b1s[col0];  chh[nt][1] = b1s[col0 + 1];
        chh[nt][2] = chh[nt][0]; chh[nt][3] = chh[nt][1];
#pragma unroll
        for (int q = 0; q < 4; q++) clo[nt][q] = 0.f;
    }
    {
        const uint32* x0 = xs + (rowb + g) * XS;
        const uint32* x1 = xs + (rowb + 8 + g) * XS;
#pragma unroll
        for (int ks = 0; ks < 2 * P; ks++) {
            int pb = ks * 8;
            uint32 ah[4], al[4];
            uint2 u;
            u = *(uint2*)(x0 + 2 * (pb + t4));     ah[0] = u.x; al[0] = u.y;
            u = *(uint2*)(x1 + 2 * (pb + t4));     ah[1] = u.x; al[1] = u.y;
            u = *(uint2*)(x0 + 2 * (pb + t4 + 4)); ah[2] = u.x; al[2] = u.y;
            u = *(uint2*)(x1 + 2 * (pb + t4 + 4)); ah[3] = u.x; al[3] = u.y;
            uint4 bh0 = *(uint4*)(w1h + (pb + t4) * 40 + g * 4);
            uint4 bh1 = *(uint4*)(w1h + (pb + t4 + 4) * 40 + g * 4);
            uint4 bl0 = *(uint4*)(w1l + (pb + t4) * 40 + g * 4);
            uint4 bl1 = *(uint4*)(w1l + (pb + t4 + 4) * 40 + g * 4);
            const uint32* bh0a = (const uint32*)&bh0;
            const uint32* bh1a = (const uint32*)&bh1;
            const uint32* bl0a = (const uint32*)&bl0;
            const uint32* bl1a = (const uint32*)&bl1;
#pragma unroll
            for (int nt = 0; nt < 4; nt++) {
                mma16(chh[nt], ah, bh0a[nt], bh1a[nt]);
                mma16(clo[nt], ah, bl0a[nt], bl1a[nt]);
                mma16(clo[nt], al, bh0a[nt], bh1a[nt]);
            }
        }
    }

    // ---- combine + tanh + layer-2 A fragments ----
    uint32 Ah[2][4], Al[2][4];
#pragma unroll
    for (int nt = 0; nt < 4; nt++) {
        float v0 = tanh_fast(chh[nt][0] + clo[nt][0]);
        float v1 = tanh_fast(chh[nt][1] + clo[nt][1]);
        float v2 = tanh_fast(chh[nt][2] + clo[nt][2]);
        float v3 = tanh_fast(chh[nt][3] + clo[nt][3]);
        int ks = nt >> 1, sl = (nt & 1) * 2;
        split2_bf16(v0, v1, Ah[ks][sl + 0], Al[ks][sl + 0]);
        split2_bf16(v2, v3, Ah[ks][sl + 1], Al[ks][sl + 1]);
    }

    // ---------------- layer 2: (dhh, dlo) ----------------
    float dhh[4][4], dlo[4][4];
#pragma unroll
    for (int nt = 0; nt < 4; nt++) {
        int col0 = nt * 8 + 2 * t4;
        dhh[nt][0] = b2s[col0];  dhh[nt][1] = b2s[col0 + 1];
        dhh[nt][2] = dhh[nt][0]; dhh[nt][3] = dhh[nt][1];
#pragma unroll
        for (int q = 0; q < 4; q++) dlo[nt][q] = 0.f;
    }
#pragma unroll
    for (int ks = 0; ks < 2; ks++) {
        int pb = ks * 8;
        uint4 bh0 = *(uint4*)(w2h + (pb + t4) * 40 + g * 4);
        uint4 bh1 = *(uint4*)(w2h + (pb + t4 + 4) * 40 + g * 4);
        uint4 bl0 = *(uint4*)(w2l + (pb + t4) * 40 + g * 4);
        uint4 bl1 = *(uint4*)(w2l + (pb + t4 + 4) * 40 + g * 4);
        const uint32* bh0a = (const uint32*)&bh0;
        const uint32* bh1a = (const uint32*)&bh1;
        const uint32* bl0a = (const uint32*)&bl0;
        const uint32* bl1a = (const uint32*)&bl1;
#pragma unroll
        for (int nt = 0; nt < 4; nt++) {
            mma16(dhh[nt], Ah[ks], bh0a[nt], bh1a[nt]);
            mma16(dlo[nt], Ah[ks], bl0a[nt], bl1a[nt]);
            mma16(dlo[nt], Al[ks], bh0a[nt], bh1a[nt]);
        }
    }

    if (SCATTER) __syncthreads();   // xs reads done before ws overwrite

    // ---- combine + store (GMEM out; SMEM staging when SCATTER) ----
    {
        int r0g = tile + rowb + g;
        int r1g = r0g + 8;
#pragma unroll
        for (int nt = 0; nt < 4; nt++) {
            int col0 = nt * 8 + 2 * t4;
            float v0 = dhh[nt][0] + dlo[nt][0];
            float v1 = dhh[nt][1] + dlo[nt][1];
            float v2 = dhh[nt][2] + dlo[nt][2];
            float v3 = dhh[nt][3] + dlo[nt][3];
            if (r0g < n)
                *(float2*)(out + (size_t)r0g * 32 + col0) = make_float2(v0, v1);
            if (r1g < n)
                *(float2*)(out + (size_t)r1g * 32 + col0) = make_float2(v2, v3);
            if (SCATTER) {
                *(float2*)(ws + (rowb + g) * 36 + col0)     = make_float2(v0, v1);
                *(float2*)(ws + (rowb + 8 + g) * 36 + col0) = make_float2(v2, v3);
            }
        }
    }

    // ---- fused scatter: cooperative float4 reds from SMEM staging ----
    if (SCATTER) {
        __syncthreads();
        int rl = tid >> 3;       // 0..31
        int c  = tid & 7;
        for (int pass = 0; pass < 4; pass++) {
            int row = rl + pass * 32;
            int r = tile + row;
            if (r < n) {
                float4 v = *(float4*)(ws + row * 36 + c * 4);
                float4* d0 = (float4*)(acc + (size_t)si0[r] * 32) + c;
                float4* d1 = (float4*)(acc + (size_t)si1[r] * 32) + c;
                atomicAdd(d0, v);
                atomicAdd(d1, v);
            }
        }
    }
}

// ---------------------------------------------------------------------------
// acc[dstidx[r]] += src[srcidx[r]]   (ring edges)
__global__ void __launch_bounds__(256) scatter1_kernel(
    const float* __restrict__ src,
    const int* __restrict__ srcidx, const int* __restrict__ dstidx,
    float* __restrict__ acc, int n)
{
    int r = blockIdx.x * 256 + threadIdx.x;
    if (r >= n) return;
    const float4* s = (const float4*)(src + (size_t)srcidx[r] * 32);
    float4* d = (float4*)(acc + (size_t)dstidx[r] * 32);
#pragma unroll
    for (int q = 0; q < 8; q++) atomicAdd(d + q, s[q]);
}

// ---------------------------------------------------------------------------
static inline int nblk256(int n)  { return (n + 255) / 256; }
static inline int nblk128t(int n) { return (n + 127) / 128; }

static inline int smem_bytes(int P)
{
    int KP = P * 16, XS = 2 * KP + 8;
    int u32s = 128 * XS + 2 * KP * 40 + 2 * 16 * 40 + 64;
    return u32s * 4;
}

extern "C" void kernel_launch(void* const* d_in, const int* in_sizes, int n_in,
                              void* d_out, int out_size)
{
    const float* h1     = (const float*)d_in[0];
    const float* h2     = (const float*)d_in[1];
    const float* h3     = (const float*)d_in[2];
    const float* h4     = (const float*)d_in[3];
    const float* upW1   = (const float*)d_in[4];
    const float* upb1   = (const float*)d_in[5];
    const float* upW2   = (const float*)d_in[6];
    const float* upb2   = (const float*)d_in[7];
    const float* dnW1   = (const float*)d_in[8];
    const float* dnb1   = (const float*)d_in[9];
    const float* dnW2   = (const float*)d_in[10];
    const float* dnb2   = (const float*)d_in[11];
    const float* rW1    = (const float*)d_in[12];
    const float* rb1    = (const float*)d_in[13];
    const float* rW2    = (const float*)d_in[14];
    const float* rb2    = (const float*)d_in[15];
    const int* idx2_0   = (const int*)d_in[16];
    const int* idx2_1   = (const int*)d_in[17];
    const int* idx3_0   = (const int*)d_in[18];
    const int* idx3_1   = (const int*)d_in[19];
    const int* idx4_0   = (const int*)d_in[20];
    const int* idx4_1   = (const int*)d_in[21];
    const int* ring_src = (const int*)d_in[22];
    const int* ring_dst = (const int*)d_in[23];

    const int N1 = in_sizes[0] / 32;
    const int N2 = in_sizes[1] / 32;
    const int N3 = in_sizes[2] / 32;
    const int N4 = in_sizes[3] / 32;
    const int ER = in_sizes[22];
    const int NR = out_size / 32 - (N1 + N2 + N3 + N4);

    float* out  = (float*)d_out;
    float* out1 = out;
    float* out2 = out1 + (size_t)N1 * 32;
    float* out3 = out2 + (size_t)N2 * 32;
    float* out4 = out3 + (size_t)N3 * 32;
    float* outR = out4 + (size_t)N4 * 32;

    float *h2buf, *h3buf, *acc3, *acc2, *acc1, *accr, *h1mid;
    cudaGetSymbolAddress((void**)&h2buf, g_h2);
    cudaGetSymbolAddress((void**)&h3buf, g_h3);
    cudaGetSymbolAddress((void**)&acc3,  g_acc3);
    cudaGetSymbolAddress((void**)&acc2,  g_acc2);
    cudaGetSymbolAddress((void**)&acc1,  g_acc1);
    cudaGetSymbolAddress((void**)&accr,  g_accr);
    cudaGetSymbolAddress((void**)&h1mid, g_h1mid);

    const int SM3 = smem_bytes(3);
    const int SM2 = smem_bytes(2);
    cudaFuncSetAttribute(mlp_bf3_kernel<3, true, true>,
        cudaFuncAttributeMaxDynamicSharedMemorySize, SM3);
    cudaFuncSetAttribute(mlp_bf3_kernel<3, true, false>,
        cudaFuncAttributeMaxDynamicSharedMemorySize, SM3);
    cudaFuncSetAttribute(mlp_bf3_kernel<2, false, true>,
        cudaFuncAttributeMaxDynamicSharedMemorySize, SM2);
    cudaFuncSetAttribute(mlp_bf3_kernel<2, false, false>,
        cudaFuncAttributeMaxDynamicSharedMemorySize, SM2);

    // ---- zero all accumulators once ----
    zero_multi_kernel<<<2048, 256>>>(
        (float4*)acc3, N3 * 8, (float4*)acc2, N2 * 8,
        (float4*)acc1, N1 * 8, (float4*)accr, N1 * 8,
        (float4*)outR, NR * 8);

    // ---- up pass ----
    mlp_bf3_kernel<3, true, false><<<nblk128t(N2), 256, SM3>>>(h2, h1,
        idx2_0, idx2_1,
        upW1 + 0 * 96 * 32, upb1 + 0 * 32, upW2 + 0 * 1024, upb2 + 0 * 32,
        h2buf, 0, 0, 0, N2);
    mlp_bf3_kernel<3, true, false><<<nblk128t(N3), 256, SM3>>>(h3, h2buf,
        idx3_0, idx3_1,
        upW1 + 1 * 96 * 32, upb1 + 1 * 32, upW2 + 1 * 1024, upb2 + 1 * 32,
        h3buf, 0, 0, 0, N3);
    // up4 + fused scatter into acc3
    mlp_bf3_kernel<3, true, true><<<nblk128t(N4), 256, SM3>>>(h4, h3buf,
        idx4_0, idx4_1,
        upW1 + 2 * 96 * 32, upb1 + 2 * 32, upW2 + 2 * 1024, upb2 + 2 * 32,
        out4, acc3, idx4_0, idx4_1, N4);

    // ---- down pass (scatter fused into producers) ----
    mlp_bf3_kernel<2, false, true><<<nblk128t(N3), 256, SM2>>>(h3buf, acc3,
        0, 0,
        dnW1 + 2 * 64 * 32, dnb1 + 2 * 32, dnW2 + 2 * 1024, dnb2 + 2 * 32,
        out3, acc2, idx3_0, idx3_1, N3);
    mlp_bf3_kernel<2, false, true><<<nblk128t(N2), 256, SM2>>>(h2buf, acc2,
        0, 0,
        dnW1 + 1 * 64 * 32, dnb1 + 1 * 32, dnW2 + 1 * 1024, dnb2 + 1 * 32,
        out2, acc1, idx2_0, idx2_1, N2);
    mlp_bf3_kernel<2, false, false><<<nblk128t(N1), 256, SM2>>>(h1, acc1,
        0, 0,
        dnW1 + 0 * 64 * 32, dnb1 + 0 * 32, dnW2 + 0 * 1024, dnb2 + 0 * 32,
        h1mid, 0, 0, 0, N1);

    // ---- ring ----
    scatter1_kernel<<<nblk256(ER), 256>>>(h1mid, ring_src, ring_dst, outR, ER);
    scatter1_kernel<<<nblk256(ER), 256>>>(outR, ring_dst, ring_src, accr, ER);
    mlp_bf3_kernel<2, false, false><<<nblk128t(N1), 256, SM2>>>(h1mid, accr,
        0, 0,
        rW1, rb1, rW2, rb2, out1, 0, 0, 0, N1);
}

// round 17
// speedup vs baseline: 1.4139x; 1.0060x over previous
#include <cuda_runtime.h>
#include <cstddef>
#include <cstdint>

// ---------------------------------------------------------------------------
// HMP hierarchical message passing — R17: R16 + cache-policy engineering.
//  * streamed self/aux reads use __ldcs (evict-first); final d_out writes use
//    st.global.cs — keeps gathered rows (h2buf/h3buf) resident in L2
//  * 256-thr blocks, 8 warps x 16 rows; bf16-split mma; fused SMEM scatter
// ---------------------------------------------------------------------------

typedef unsigned int uint32;

#define N1MAX 250000
#define N2MAX 500000
#define N3MAX 1000000

__device__ float g_h2   [(size_t)N2MAX * 32];
__device__ float g_h3   [(size_t)N3MAX * 32];
__device__ float g_acc3 [(size_t)N3MAX * 32];
__device__ float g_acc2 [(size_t)N2MAX * 32];
__device__ float g_acc1 [(size_t)N1MAX * 32];
__device__ float g_accr [(size_t)N1MAX * 32];
__device__ float g_h1mid[(size_t)N1MAX * 32];

// ---------------------------------------------------------------------------
__device__ __forceinline__ float tanh_fast(float x)
{
    float cx = fminf(fmaxf(x, -15.f), 15.f);
    float e  = __expf(2.f * cx);
    return __fdividef(e - 1.f, e + 1.f);
}

__device__ __forceinline__ void split2_bf16(float v0, float v1,
                                            uint32& hi, uint32& lo)
{
    uint32 u0 = __float_as_uint(v0), u1 = __float_as_uint(v1);
    hi = (u1 & 0xFFFF0000u) | (u0 >> 16);
    float l0 = v0 - __uint_as_float(u0 & 0xFFFF0000u);
    float l1 = v1 - __uint_as_float(u1 & 0xFFFF0000u);
    asm("cvt.rn.bf16x2.f32 %0, %1, %2;" : "=r"(lo) : "f"(l1), "f"(l0));
}

__device__ __forceinline__ void mma16(float c[4], const uint32 a[4],
                                      uint32 b0, uint32 b1)
{
    asm volatile(
        "mma.sync.aligned.m16n8k16.row.col.f32.bf16.bf16.f32 "
        "{%0,%1,%2,%3},{%4,%5,%6,%7},{%8,%9},{%0,%1,%2,%3};"
        : "+f"(c[0]), "+f"(c[1]), "+f"(c[2]), "+f"(c[3])
        : "r"(a[0]), "r"(a[1]), "r"(a[2]), "r"(a[3]), "r"(b0), "r"(b1));
}

// evict-first vector store (for final outputs, never re-read)
__device__ __forceinline__ void stcs2(float* p, float a, float b)
{
    asm volatile("st.global.cs.v2.f32 [%0], {%1, %2};"
                 :: "l"(p), "f"(a), "f"(b) : "memory");
}

// ---------------------------------------------------------------------------
__global__ void __launch_bounds__(256) zero_multi_kernel(
    float4* __restrict__ p0, int n0, float4* __restrict__ p1, int n1,
    float4* __restrict__ p2, int n2, float4* __restrict__ p3, int n3,
    float4* __restrict__ p4, int n4)
{
    const float4 z = make_float4(0.f, 0.f, 0.f, 0.f);
    int total = n0 + n1 + n2 + n3 + n4;
    for (int i = blockIdx.x * 256 + threadIdx.x; i < total; i += gridDim.x * 256) {
        int j = i;
        if (j < n0) { p0[j] = z; continue; } j -= n0;
        if (j < n1) { p1[j] = z; continue; } j -= n1;
        if (j < n2) { p2[j] = z; continue; } j -= n2;
        if (j < n3) { p3[j] = z; continue; } j -= n3;
        p4[j] = z;
    }
}

// ---------------------------------------------------------------------------
// bf16-split tensor-core MLP, optional fused scatter, cache-policy hints.
// SOUT: out region is final (never re-read) -> evict-first stores.
template<int P, bool GATHER, bool SCATTER, bool SOUT>
__global__ void __launch_bounds__(256) mlp_bf3_kernel(
    const float* __restrict__ self, const float* __restrict__ other,
    const int* __restrict__ gi0, const int* __restrict__ gi1,
    const float* __restrict__ W1, const float* __restrict__ b1,
    const float* __restrict__ W2, const float* __restrict__ b2,
    float* __restrict__ out,
    float* __restrict__ acc,
    const int* __restrict__ si0, const int* __restrict__ si1,
    int n)
{
    extern __shared__ uint32 smu[];
    const int KP = P * 16;
    const int XS = 2 * KP + 8;
    uint32* xs  = smu;                         // [128][XS] interleaved hi/lo
    uint32* w1h = xs + 128 * XS;               // [KP][40]
    uint32* w1l = w1h + KP * 40;
    uint32* w2h = w1l + KP * 40;               // [16][40]
    uint32* w2l = w2h + 16 * 40;
    float*  b1s = (float*)(w2l + 16 * 40);     // [32]
    float*  b2s = b1s + 32;                    // [32]
    float*  ws  = (float*)xs;                  // scatter staging [128][36]

    int tid  = threadIdx.x;
    int tile = blockIdx.x * 128;

    // ---- weights: load + bf16 split, nt-interleaved layout ----
    for (int idx = tid; idx < KP * 32; idx += 256) {
        int p = idx >> 5, nn = idx & 31;
        float v0 = W1[(2 * p) * 32 + nn];
        float v1 = W1[(2 * p + 1) * 32 + nn];
        uint32 hi, lo; split2_bf16(v0, v1, hi, lo);
        int o = p * 40 + (nn & 7) * 4 + (nn >> 3);
        w1h[o] = hi; w1l[o] = lo;
    }
    for (int idx = tid; idx < 16 * 32; idx += 256) {
        int p = idx >> 5, nn = idx & 31;
        float v0 = W2[(2 * p) * 32 + nn];
        float v1 = W2[(2 * p + 1) * 32 + nn];
        uint32 hi, lo; split2_bf16(v0, v1, hi, lo);
        int o = p * 40 + (nn & 7) * 4 + (nn >> 3);
        w2h[o] = hi; w2l[o] = lo;
    }
    if (tid < 32) { b1s[tid] = b1[tid]; b2s[tid] = b2[tid]; }

    // ---- stage x tile (streamed rows: evict-first; gathers: default) ----
    {
        int rl = tid >> 3;
        int c  = tid & 7;
        for (int pass = 0; pass < 4; pass++) {
            int row = rl + pass * 32;
            int r = min(tile + row, n - 1);
#pragma unroll
            for (int p = 0; p < P; p++) {
                float4 v;
                if (p == 0) {
                    v = __ldcs((const float4*)(self + (size_t)r * 32) + c);
                } else if (GATHER) {
                    const float* src = other +
                        (size_t)((p == 1) ? gi0[r] : gi1[r]) * 32;
                    v = __ldg((const float4*)src + c);
                } else {
                    v = __ldcs((const float4*)(other + (size_t)r * 32) + c);
                }
                uint32 h0, l0, h1, l1;
                split2_bf16(v.x, v.y, h0, l0);
                split2_bf16(v.z, v.w, h1, l1);
                uint4 w4; w4.x = h0; w4.y = l0; w4.z = h1; w4.w = l1;
                *(uint4*)(xs + row * XS + (p * 16 + 2 * c) * 2) = w4;
            }
        }
    }
    __syncthreads();

    int lane = tid & 31;
    int warp = tid >> 5;
    int g    = lane >> 2;
    int t4   = lane & 3;
    int rowb = warp * 16;

    // ---------------- layer 1: (chh, clo) ----------------
    float chh[4][4], clo[4][4];
#pragma unroll
    for (int nt = 0; nt < 4; nt++) {
        int col0 = nt * 8 + 2 * t4;
        chh[nt][0] = b1s[col0];  chh[nt][1] = b1s[col0 + 1];
        chh[nt][2] = chh[nt][0]; chh[nt][3] = chh[nt][1];
#pragma unroll
        for (int q = 0; q < 4; q++) clo[nt][q] = 0.f;
    }
    {
        const uint32* x0 = xs + (rowb + g) * XS;
        const uint32* x1 = xs + (rowb + 8 + g) * XS;
#pragma unroll
        for (int ks = 0; ks < 2 * P; ks++) {
            int pb = ks * 8;
            uint32 ah[4], al[4];
            uint2 u;
            u = *(uint2*)(x0 + 2 * (pb + t4));     ah[0] = u.x; al[0] = u.y;
            u = *(uint2*)(x1 + 2 * (pb + t4));     ah[1] = u.x; al[1] = u.y;
            u = *(uint2*)(x0 + 2 * (pb + t4 + 4)); ah[2] = u.x; al[2] = u.y;
            u = *(uint2*)(x1 + 2 * (pb + t4 + 4)); ah[3] = u.x; al[3] = u.y;
            uint4 bh0 = *(uint4*)(w1h + (pb + t4) * 40 + g * 4);
            uint4 bh1 = *(uint4*)(w1h + (pb + t4 + 4) * 40 + g * 4);
            uint4 bl0 = *(uint4*)(w1l + (pb + t4) * 40 + g * 4);
            uint4 bl1 = *(uint4*)(w1l + (pb + t4 + 4) * 40 + g * 4);
            const uint32* bh0a = (const uint32*)&bh0;
            const uint32* bh1a = (const uint32*)&bh1;
            const uint32* bl0a = (const uint32*)&bl0;
            const uint32* bl1a = (const uint32*)&bl1;
#pragma unroll
            for (int nt = 0; nt < 4; nt++) {
                mma16(chh[nt], ah, bh0a[nt], bh1a[nt]);
                mma16(clo[nt], ah, bl0a[nt], bl1a[nt]);
                mma16(clo[nt], al, bh0a[nt], bh1a[nt]);
            }
        }
    }

    // ---- combine + tanh + layer-2 A fragments ----
    uint32 Ah[2][4], Al[2][4];
#pragma unroll
    for (int nt = 0; nt < 4; nt++) {
        float v0 = tanh_fast(chh[nt][0] + clo[nt][0]);
        float v1 = tanh_fast(chh[nt][1] + clo[nt][1]);
        float v2 = tanh_fast(chh[nt][2] + clo[nt][2]);
        float v3 = tanh_fast(chh[nt][3] + clo[nt][3]);
        int ks = nt >> 1, sl = (nt & 1) * 2;
        split2_bf16(v0, v1, Ah[ks][sl + 0], Al[ks][sl + 0]);
        split2_bf16(v2, v3, Ah[ks][sl + 1], Al[ks][sl + 1]);
    }

    // ---------------- layer 2: (dhh, dlo) ----------------
    float dhh[4][4], dlo[4][4];
#pragma unroll
    for (int nt = 0; nt < 4; nt++) {
        int col0 = nt * 8 + 2 * t4;
        dhh[nt][0] = b2s[col0];  dhh[nt][1] = b2s[col0 + 1];
        dhh[nt][2] = dhh[nt][0]; dhh[nt][3] = dhh[nt][1];
#pragma unroll
        for (int q = 0; q < 4; q++) dlo[nt][q] = 0.f;
    }
#pragma unroll
    for (int ks = 0; ks < 2; ks++) {
        int pb = ks * 8;
        uint4 bh0 = *(uint4*)(w2h + (pb + t4) * 40 + g * 4);
        uint4 bh1 = *(uint4*)(w2h + (pb + t4 + 4) * 40 + g * 4);
        uint4 bl0 = *(uint4*)(w2l + (pb + t4) * 40 + g * 4);
        uint4 bl1 = *(uint4*)(w2l + (pb + t4 + 4) * 40 + g * 4);
        const uint32* bh0a = (const uint32*)&bh0;
        const uint32* bh1a = (const uint32*)&bh1;
        const uint32* bl0a = (const uint32*)&bl0;
        const uint32* bl1a = (const uint32*)&bl1;
#pragma unroll
        for (int nt = 0; nt < 4; nt++) {
            mma16(dhh[nt], Ah[ks], bh0a[nt], bh1a[nt]);
            mma16(dlo[nt], Ah[ks], bl0a[nt], bl1a[nt]);
            mma16(dlo[nt], Al[ks], bh0a[nt], bh1a[nt]);
        }
    }

    if (SCATTER) __syncthreads();   // xs reads done before ws overwrite

    // ---- combine + store ----
    {
        int r0g = tile + rowb + g;
        int r1g = r0g + 8;
#pragma unroll
        for (int nt = 0; nt < 4; nt++) {
            int col0 = nt * 8 + 2 * t4;
            float v0 = dhh[nt][0] + dlo[nt][0];
            float v1 = dhh[nt][1] + dlo[nt][1];
            float v2 = dhh[nt][2] + dlo[nt][2];
            float v3 = dhh[nt][3] + dlo[nt][3];
            if (r0g < n) {
                float* p = out + (size_t)r0g * 32 + col0;
                if (SOUT) stcs2(p, v0, v1);
                else      *(float2*)p = make_float2(v0, v1);
            }
            if (r1g < n) {
                float* p = out + (size_t)r1g * 32 + col0;
                if (SOUT) stcs2(p, v2, v3);
                else      *(float2*)p = make_float2(v2, v3);
            }
            if (SCATTER) {
                *(float2*)(ws + (rowb + g) * 36 + col0)     = make_float2(v0, v1);
                *(float2*)(ws + (rowb + 8 + g) * 36 + col0) = make_float2(v2, v3);
            }
        }
    }

    // ---- fused scatter: cooperative float4 reds from SMEM staging ----
    if (SCATTER) {
        __syncthreads();
        int rl = tid >> 3;
        int c  = tid & 7;
        for (int pass = 0; pass < 4; pass++) {
            int row = rl + pass * 32;
            int r = tile + row;
            if (r < n) {
                float4 v = *(float4*)(ws + row * 36 + c * 4);
                float4* d0 = (float4*)(acc + (size_t)si0[r] * 32) + c;
                float4* d1 = (float4*)(acc + (size_t)si1[r] * 32) + c;
                atomicAdd(d0, v);
                atomicAdd(d1, v);
            }
        }
    }
}

// ---------------------------------------------------------------------------
// acc[dstidx[r]] += src[srcidx[r]]   (ring edges)
__global__ void __launch_bounds__(256) scatter1_kernel(
    const float* __restrict__ src,
    const int* __restrict__ srcidx, const int* __restrict__ dstidx,
    float* __restrict__ acc, int n)
{
    int r = blockIdx.x * 256 + threadIdx.x;
    if (r >= n) return;
    const float4* s = (const float4*)(src + (size_t)srcidx[r] * 32);
    float4* d = (float4*)(acc + (size_t)dstidx[r] * 32);
#pragma unroll
    for (int q = 0; q < 8; q++) atomicAdd(d + q, s[q]);
}

// ---------------------------------------------------------------------------
static inline int nblk256(int n)  { return (n + 255) / 256; }
static inline int nblk128t(int n) { return (n + 127) / 128; }

static inline int smem_bytes(int P)
{
    int KP = P * 16, XS = 2 * KP + 8;
    int u32s = 128 * XS + 2 * KP * 40 + 2 * 16 * 40 + 64;
    return u32s * 4;
}

extern "C" void kernel_launch(void* const* d_in, const int* in_sizes, int n_in,
                              void* d_out, int out_size)
{
    const float* h1     = (const float*)d_in[0];
    const float* h2     = (const float*)d_in[1];
    const float* h3     = (const float*)d_in[2];
    const float* h4     = (const float*)d_in[3];
    const float* upW1   = (const float*)d_in[4];
    const float* upb1   = (const float*)d_in[5];
    const float* upW2   = (const float*)d_in[6];
    const float* upb2   = (const float*)d_in[7];
    const float* dnW1   = (const float*)d_in[8];
    const float* dnb1   = (const float*)d_in[9];
    const float* dnW2   = (const float*)d_in[10];
    const float* dnb2   = (const float*)d_in[11];
    const float* rW1    = (const float*)d_in[12];
    const float* rb1    = (const float*)d_in[13];
    const float* rW2    = (const float*)d_in[14];
    const float* rb2    = (const float*)d_in[15];
    const int* idx2_0   = (const int*)d_in[16];
    const int* idx2_1   = (const int*)d_in[17];
    const int* idx3_0   = (const int*)d_in[18];
    const int* idx3_1   = (const int*)d_in[19];
    const int* idx4_0   = (const int*)d_in[20];
    const int* idx4_1   = (const int*)d_in[21];
    const int* ring_src = (const int*)d_in[22];
    const int* ring_dst = (const int*)d_in[23];

    const int N1 = in_sizes[0] / 32;
    const int N2 = in_sizes[1] / 32;
    const int N3 = in_sizes[2] / 32;
    const int N4 = in_sizes[3] / 32;
    const int ER = in_sizes[22];
    const int NR = out_size / 32 - (N1 + N2 + N3 + N4);

    float* out  = (float*)d_out;
    float* out1 = out;
    float* out2 = out1 + (size_t)N1 * 32;
    float* out3 = out2 + (size_t)N2 * 32;
    float* out4 = out3 + (size_t)N3 * 32;
    float* outR = out4 + (size_t)N4 * 32;

    float *h2buf, *h3buf, *acc3, *acc2, *acc1, *accr, *h1mid;
    cudaGetSymbolAddress((void**)&h2buf, g_h2);
    cudaGetSymbolAddress((void**)&h3buf, g_h3);
    cudaGetSymbolAddress((void**)&acc3,  g_acc3);
    cudaGetSymbolAddress((void**)&acc2,  g_acc2);
    cudaGetSymbolAddress((void**)&acc1,  g_acc1);
    cudaGetSymbolAddress((void**)&accr,  g_accr);
    cudaGetSymbolAddress((void**)&h1mid, g_h1mid);

    const int SM3 = smem_bytes(3);
    const int SM2 = smem_bytes(2);
    cudaFuncSetAttribute(mlp_bf3_kernel<3, true, false, false>,
        cudaFuncAttributeMaxDynamicSharedMemorySize, SM3);
    cudaFuncSetAttribute(mlp_bf3_kernel<3, true, true, true>,
        cudaFuncAttributeMaxDynamicSharedMemorySize, SM3);
    cudaFuncSetAttribute(mlp_bf3_kernel<2, false, true, true>,
        cudaFuncAttributeMaxDynamicSharedMemorySize, SM2);
    cudaFuncSetAttribute(mlp_bf3_kernel<2, false, false, false>,
        cudaFuncAttributeMaxDynamicSharedMemorySize, SM2);
    cudaFuncSetAttribute(mlp_bf3_kernel<2, false, false, true>,
        cudaFuncAttributeMaxDynamicSharedMemorySize, SM2);

    // ---- zero all accumulators once ----
    zero_multi_kernel<<<2048, 256>>>(
        (float4*)acc3, N3 * 8, (float4*)acc2, N2 * 8,
        (float4*)acc1, N1 * 8, (float4*)accr, N1 * 8,
        (float4*)outR, NR * 8);

    // ---- up pass ----
    mlp_bf3_kernel<3, true, false, false><<<nblk128t(N2), 256, SM3>>>(h2, h1,
        idx2_0, idx2_1,
        upW1 + 0 * 96 * 32, upb1 + 0 * 32, upW2 + 0 * 1024, upb2 + 0 * 32,
        h2buf, 0, 0, 0, N2);
    mlp_bf3_kernel<3, true, false, false><<<nblk128t(N3), 256, SM3>>>(h3, h2buf,
        idx3_0, idx3_1,
        upW1 + 1 * 96 * 32, upb1 + 1 * 32, upW2 + 1 * 1024, upb2 + 1 * 32,
        h3buf, 0, 0, 0, N3);
    // up4 + fused scatter into acc3 (out4 is final -> evict-first stores)
    mlp_bf3_kernel<3, true, true, true><<<nblk128t(N4), 256, SM3>>>(h4, h3buf,
        idx4_0, idx4_1,
        upW1 + 2 * 96 * 32, upb1 + 2 * 32, upW2 + 2 * 1024, upb2 + 2 * 32,
        out4, acc3, idx4_0, idx4_1, N4);

    // ---- down pass (scatter fused; out3/out2 final -> evict-first) ----
    mlp_bf3_kernel<2, false, true, true><<<nblk128t(N3), 256, SM2>>>(h3buf, acc3,
        0, 0,
        dnW1 + 2 * 64 * 32, dnb1 + 2 * 32, dnW2 + 2 * 1024, dnb2 + 2 * 32,
        out3, acc2, idx3_0, idx3_1, N3);
    mlp_bf3_kernel<2, false, true, true><<<nblk128t(N2), 256, SM2>>>(h2buf, acc2,
        0, 0,
        dnW1 + 1 * 64 * 32, dnb1 + 1 * 32, dnW2 + 1 * 1024, dnb2 + 1 * 32,
        out2, acc1, idx2_0, idx2_1, N2);
    mlp_bf3_kernel<2, false, false, false><<<nblk128t(N1), 256, SM2>>>(h1, acc1,
        0, 0,
        dnW1 + 0 * 64 * 32, dnb1 + 0 * 32, dnW2 + 0 * 1024, dnb2 + 0 * 32,
        h1mid, 0, 0, 0, N1);

    // ---- ring ----
    scatter1_kernel<<<nblk256(ER), 256>>>(h1mid, ring_src, ring_dst, outR, ER);
    scatter1_kernel<<<nblk256(ER), 256>>>(outR, ring_dst, ring_src, accr, ER);
    mlp_bf3_kernel<2, false, false, true><<<nblk128t(N1), 256, SM2>>>(h1mid, accr,
        0, 0,
        rW1, rb1, rW2, rb2, out1, 0, 0, 0, N1);
}